// round 7
// baseline (speedup 1.0000x reference)
#include <cuda_runtime.h>
#include <cuda_fp16.h>
#include <cstdint>

#define E_NUM 32
#define DK 1024
#define DN 1024
#define BM 128
#define BN 128
#define KC 32            /* fp16 per K-chunk = 64 bytes (half of a 128B physical row) */
#define NCHUNK (DK / KC) /* 32 */
#define PSTAGES 3        /* physical 128B-row stages; 6 half-slots */
#define NSLOT 6
#define MT_CAP 1152

/* ---------------- scratch (device globals; no allocation APIs) -------------- */
static __device__ __align__(1024) __half g_Wh[(long long)E_NUM * DN * DK];  /* 64 MB */
static __device__ int g_tile_expert[MT_CAP];
static __device__ int g_tile_row[MT_CAP];
static __device__ int g_tile_nrows[MT_CAP];
static __device__ int g_num_mtiles;

/* ---------------- helpers ---------------- */
static __device__ __forceinline__ uint32_t smem_u32(const void* p) {
    uint32_t a;
    asm("{ .reg .u64 t; cvta.to.shared.u64 t, %1; cvt.u32.u64 %0, t; }" : "=r"(a) : "l"(p));
    return a;
}
static __device__ __forceinline__ void cp16(uint32_t dst, const void* src) {
    asm volatile("cp.async.cg.shared.global [%0], [%1], 16;\n" :: "r"(dst), "l"(src));
}
static __device__ __forceinline__ void cp_async_arrive(uint32_t mbar) {
    asm volatile("cp.async.mbarrier.arrive.noinc.shared.b64 [%0];" :: "r"(mbar) : "memory");
}

#define MBARRIER_INIT(addr, cnt) \
    asm volatile("mbarrier.init.shared.b64 [%0], %1;" :: "r"((uint32_t)(addr)), "r"((uint32_t)(cnt)) : "memory")
#define MBARRIER_ARRIVE(addr) \
    asm volatile("mbarrier.arrive.shared.b64 _, [%0];" :: "r"((uint32_t)(addr)) : "memory")

#define MBARRIER_WAIT_PARITY(mbar_smem_addr, phase_parity) do {                                   \
    uint32_t _mbar = (uint32_t)(mbar_smem_addr);                                                  \
    uint32_t _parity = (uint32_t)(phase_parity);                                                  \
    uint32_t _done;                                                                               \
    asm volatile(                                                                                 \
        "{\n\t"                                                                                   \
        ".reg .pred p;\n\t"                                                                       \
        "mbarrier.try_wait.parity.acquire.cta.shared::cta.b64 p, [%1], %2;\n\t"                   \
        "selp.b32 %0, 1, 0, p;\n\t"                                                               \
        "}"                                                                                       \
        : "=r"(_done) : "r"(_mbar), "r"(_parity) : "memory");                                     \
    if (!_done) {                                                                                 \
        asm volatile(                                                                             \
            "{\n\t"                                                                               \
            ".reg .pred P1;\n\t"                                                                  \
            "WAIT_LOOP_%=:\n\t"                                                                   \
            "mbarrier.try_wait.parity.acquire.cta.shared::cta.b64 P1, [%0], %1, 0x989680;\n\t"    \
            "@P1 bra.uni WAIT_DONE_%=;\n\t"                                                       \
            "bra.uni WAIT_LOOP_%=;\n\t"                                                           \
            "WAIT_DONE_%=:\n\t"                                                                   \
            "}"                                                                                   \
            :: "r"(_mbar), "r"(_parity) : "memory");                                              \
    }                                                                                             \
} while (0)

#define LDSM_X4(r0, r1, r2, r3, addr) \
    asm volatile("ldmatrix.sync.aligned.m8n8.x4.shared.b16 {%0,%1,%2,%3}, [%4];" \
                 : "=r"(r0), "=r"(r1), "=r"(r2), "=r"(r3) : "r"(addr))

#define MMA16816(c0, c1, c2, c3, a0, a1, a2, a3, b0, b1) \
    asm volatile("mma.sync.aligned.m16n8k16.row.col.f32.f16.f16.f32 " \
                 "{%0,%1,%2,%3}, {%4,%5,%6,%7}, {%8,%9}, {%0,%1,%2,%3};" \
                 : "+f"(c0), "+f"(c1), "+f"(c2), "+f"(c3) \
                 : "r"(a0), "r"(a1), "r"(a2), "r"(a3), "r"(b0), "r"(b1))

#define STS128(addr, u0, u1, u2, u3) \
    asm volatile("st.shared.v4.b32 [%0], {%1,%2,%3,%4};" \
                 :: "r"(addr), "r"(u0), "r"(u1), "r"(u2), "r"(u3) : "memory")

/* ---------------- pre-pass: W fp32->fp16 only -------------------------------- */
__global__ void cvtW_kernel(const float4* __restrict__ src, long long n4) {
    long long i = (long long)blockIdx.x * blockDim.x + threadIdx.x;
    long long stride = (long long)gridDim.x * blockDim.x;
    uint2* dst = reinterpret_cast<uint2*>(g_Wh);
    for (; i < n4; i += stride) {
        float4 v = src[i];
        __half2 h0 = __floats2half2_rn(v.x, v.y);
        __half2 h1 = __floats2half2_rn(v.z, v.w);
        uint2 u;
        u.x = *reinterpret_cast<uint32_t*>(&h0);
        u.y = *reinterpret_cast<uint32_t*>(&h1);
        dst[i] = u;
    }
}

/* Build tile table. Handles expert_frequency delivered as int32 OR int64. */
__global__ void build_tiles_kernel(const int* __restrict__ ef, int T_tokens) {
    if (threadIdx.x != 0 || blockIdx.x != 0) return;
    long long s = 0;
    for (int i = 0; i < E_NUM; i++) s += ef[i];
    bool is64 = (s != (long long)T_tokens);
    long long off = 0;
    int t = 0;
    for (int e = 0; e < E_NUM; e++) {
        long long c;
        if (is64)
            c = (long long)(unsigned)ef[2 * e] | ((long long)ef[2 * e + 1] << 32);
        else
            c = ef[e];
        for (long long m = 0; m < c; m += BM) {
            long long rem = c - m;
            g_tile_expert[t] = e;
            g_tile_row[t]    = (int)(off + m);
            g_tile_nrows[t]  = (int)(rem < BM ? rem : BM);
            t++;
        }
        off += c;
    }
    g_num_mtiles = t;
}

/* ---------------- main grouped-GEMM (mma.sync fp16, fused A conversion) -----
   CTA 128x128, 8 warps (4m x 2n), warp 32x64, 2 CTAs/SM.
   K split into 32 chunks of 32 cols; chunks packed 2-per-128B-row into 3
   physical stages -> 6 half-slots. Producer path per chunk:
     A: LDG fp32 (4 x float4, issued one iter early), cvt, STS fp16 (+release
        arrive);  B: 2 x cp.async fp16 (+async arrive).
   full[slot]: count 512 (256 cp-arrives + 256 STS-arrives)
   empty[slot]: count 8 (one per warp after its MMAs).                        */

#define STAGE_BYTES 32768              /* A 16KB + B 16KB (128B rows) */
#define MBAR_BYTES  1024
#define SMEM_TOTAL  (PSTAGES * STAGE_BYTES + MBAR_BYTES)
/* mbar layout: full[s] at +s*8 (s=0..5); empty[s] at +64+s*8 */

struct AH { float4 q0, q1, q2, q3; };

static __device__ __forceinline__ void ldgA(AH* h, const float* gA32, int c, int colh, bool valid) {
    if (valid) {
        const float4* p = (const float4*)(gA32 + c * KC + colh * 16);
        h->q0 = p[0]; h->q1 = p[1]; h->q2 = p[2]; h->q3 = p[3];
    } else {
        h->q0 = h->q1 = h->q2 = h->q3 = make_float4(0.f, 0.f, 0.f, 0.f);
    }
}

static __device__ __forceinline__ void stsA(const AH* h, uint32_t sA, int c, int row, int colh) {
    const uint32_t xorv = (uint32_t)(row & 7) * 16u;
    const uint32_t base = (uint32_t)row * 128u + (uint32_t)((c & 1) * 64 + colh * 32);
    uint32_t u[8];
    __half2 t;
    t = __floats2half2_rn(h->q0.x, h->q0.y); u[0] = *(uint32_t*)&t;
    t = __floats2half2_rn(h->q0.z, h->q0.w); u[1] = *(uint32_t*)&t;
    t = __floats2half2_rn(h->q1.x, h->q1.y); u[2] = *(uint32_t*)&t;
    t = __floats2half2_rn(h->q1.z, h->q1.w); u[3] = *(uint32_t*)&t;
    t = __floats2half2_rn(h->q2.x, h->q2.y); u[4] = *(uint32_t*)&t;
    t = __floats2half2_rn(h->q2.z, h->q2.w); u[5] = *(uint32_t*)&t;
    t = __floats2half2_rn(h->q3.x, h->q3.y); u[6] = *(uint32_t*)&t;
    t = __floats2half2_rn(h->q3.z, h->q3.w); u[7] = *(uint32_t*)&t;
    uint32_t a0 = sA + (((base)      ) ^ xorv);
    uint32_t a1 = sA + (((base + 16u)) ^ xorv);
    STS128(a0, u[0], u[1], u[2], u[3]);
    STS128(a1, u[4], u[5], u[6], u[7]);
}

static __device__ __forceinline__ void cpB(uint32_t sB, const __half* gBrow, int c, int row, int colh) {
    const uint32_t xorv = (uint32_t)(row & 7) * 16u;
    const uint32_t base = (uint32_t)row * 128u + (uint32_t)((c & 1) * 64 + colh * 32);
    const char* src = (const char*)(gBrow + c * KC + colh * 16);
    cp16(sB + ((base       ) ^ xorv), src);
    cp16(sB + ((base + 16u ) ^ xorv), src + 16);
}

__global__ void __launch_bounds__(256, 2) gemm_kernel(
    const float* __restrict__ x, const float* __restrict__ bias,
    float* __restrict__ out, int T_tokens)
{
    extern __shared__ __align__(1024) char smem[];
    const int nt = blockIdx.x;           /* fast dim: 8 N-tiles share A in L2 */
    const int mt = blockIdx.y;
    if (mt >= g_num_mtiles) return;

    const int e     = g_tile_expert[mt];
    const int row0  = g_tile_row[mt];
    const int nrows = g_tile_nrows[mt];

    const uint32_t smem_base = smem_u32(smem);
    const uint32_t mbar_base = smem_base + PSTAGES * STAGE_BYTES;
    const int tid  = threadIdx.x;
    const int lane = tid & 31;
    const int wid  = tid >> 5;
    const int warp_m = wid >> 1;
    const int warp_n = wid & 1;

    if (tid == 0) {
#pragma unroll
        for (int s = 0; s < NSLOT; s++) {
            MBARRIER_INIT(mbar_base + s * 8, 512);        /* full  */
            MBARRIER_INIT(mbar_base + 64 + s * 8, 8);     /* empty */
        }
    }
    __syncthreads();

    /* producer thread mapping: row = tid>>1 (shared by A and B), colh = tid&1 */
    const int prow = tid >> 1;
    const int colh = tid & 1;
    const bool avalid = (row0 + prow < T_tokens);
    const float*  gA32 = x + (size_t)(avalid ? (row0 + prow) : 0) * DK;
    const __half* gBrow = g_Wh + ((size_t)e * DN + (size_t)nt * BN + prow) * DK;

    /* stage base addresses per half-slot */
    uint32_t sAo[NSLOT], sBo[NSLOT];
#pragma unroll
    for (int s = 0; s < NSLOT; s++) {
        sAo[s] = smem_base + (uint32_t)((s >> 1) % PSTAGES) * STAGE_BYTES;
        sBo[s] = sAo[s] + 16384u;
    }

    /* ldmatrix per-lane address components */
    uint32_t aRow[2], aXor[2];
#pragma unroll
    for (int mf = 0; mf < 2; mf++) {
        int r = warp_m * 32 + mf * 16 + (lane & 15);
        aRow[mf] = (uint32_t)r * 128u;
        aXor[mf] = (uint32_t)(r & 7) * 16u;
    }
    const uint32_t aHi = (uint32_t)((lane >> 4) & 1) * 16u;

    uint32_t bRow[4], bXor[4];
#pragma unroll
    for (int g = 0; g < 4; g++) {
        int r = warp_n * 64 + g * 16 + (lane & 7) + (((lane >> 4) & 1) << 3);
        bRow[g] = (uint32_t)r * 128u;
        bXor[g] = (uint32_t)(r & 7) * 16u;
    }
    const uint32_t bHi = (uint32_t)((lane >> 3) & 1) * 16u;

    /* ---- prologue: produce chunks 0..3, prefetch A regs for chunk 4 ---- */
    {
#pragma unroll
        for (int j = 0; j < 4; j++) {
            cpB(sBo[j], gBrow, j, prow, colh);
            cp_async_arrive(mbar_base + j * 8);
        }
        AH h0, h1;
        ldgA(&h0, gA32, 0, colh, avalid);
        ldgA(&h1, gA32, 1, colh, avalid);
        stsA(&h0, sAo[0], 0, prow, colh); MBARRIER_ARRIVE(mbar_base + 0 * 8);
        stsA(&h1, sAo[1], 1, prow, colh); MBARRIER_ARRIVE(mbar_base + 1 * 8);
        ldgA(&h0, gA32, 2, colh, avalid);
        ldgA(&h1, gA32, 3, colh, avalid);
        stsA(&h0, sAo[2], 2, prow, colh); MBARRIER_ARRIVE(mbar_base + 2 * 8);
        stsA(&h1, sAo[3], 3, prow, colh); MBARRIER_ARRIVE(mbar_base + 3 * 8);
    }

    AH hA;                                  /* carried A fp32 for chunk c+4 */
    ldgA(&hA, gA32, 4, colh, avalid);

    float acc[2][8][4];
#pragma unroll
    for (int mf = 0; mf < 2; mf++)
#pragma unroll
        for (int nf = 0; nf < 8; nf++)
#pragma unroll
            for (int k = 0; k < 4; k++) acc[mf][nf][k] = 0.0f;

    uint32_t fullph = 0, emptyph = 0;

#pragma unroll 1
    for (int c = 0; c < NCHUNK; c++) {
        const int s = c % NSLOT;

        /* ---- consume chunk c ---- */
        MBARRIER_WAIT_PARITY(mbar_base + s * 8, (fullph >> s) & 1);
        fullph ^= (1u << s);

        const uint32_t sA = sAo[s];
        const uint32_t sB = sBo[s];
        const uint32_t kbase = (uint32_t)(c & 1) * 64u;

#pragma unroll
        for (int ks = 0; ks < 2; ks++) {
            const uint32_t kb = kbase + (uint32_t)ks * 32u;
            uint32_t a[2][4];
#pragma unroll
            for (int mf = 0; mf < 2; mf++) {
                uint32_t addr = sA + aRow[mf] + ((kb + aHi) ^ aXor[mf]);
                LDSM_X4(a[mf][0], a[mf][1], a[mf][2], a[mf][3], addr);
            }
            uint32_t b[4][4];
#pragma unroll
            for (int g = 0; g < 4; g++) {
                uint32_t addr = sB + bRow[g] + ((kb + bHi) ^ bXor[g]);
                LDSM_X4(b[g][0], b[g][1], b[g][2], b[g][3], addr);
            }
#pragma unroll
            for (int mf = 0; mf < 2; mf++) {
#pragma unroll
                for (int nf = 0; nf < 8; nf++) {
                    const int g  = nf >> 1;
                    const int hi = (nf & 1) * 2;
                    MMA16816(acc[mf][nf][0], acc[mf][nf][1], acc[mf][nf][2], acc[mf][nf][3],
                             a[mf][0], a[mf][1], a[mf][2], a[mf][3],
                             b[g][hi], b[g][hi + 1]);
                }
            }
        }
        if (lane == 0) MBARRIER_ARRIVE(mbar_base + 64 + s * 8);

        /* ---- produce chunk c+4 (A regs were loaded one iter ago) ---- */
        if (c + 4 < NCHUNK) {
            const int q  = c + 4;
            const int qs = q % NSLOT;
            if (c >= 2) {   /* slots 0..5 first used by chunks 0..5: no wait */
                MBARRIER_WAIT_PARITY(mbar_base + 64 + qs * 8, (emptyph >> qs) & 1);
                emptyph ^= (1u << qs);
            }
            stsA(&hA, sAo[qs], q, prow, colh);
            MBARRIER_ARRIVE(mbar_base + qs * 8);             /* release: covers STS */
            cpB(sBo[qs], gBrow, q, prow, colh);
            cp_async_arrive(mbar_base + qs * 8);
        }
        /* ---- prefetch A fp32 for chunk c+5 ---- */
        if (c + 5 < NCHUNK)
            ldgA(&hA, gA32, c + 5, colh, avalid);
    }

    /* ---- epilogue: out = acc + bias ---- */
    const int colBase = nt * BN + warp_n * 64 + (lane & 3) * 2;
    const float* brow = bias + (size_t)e * DN;
#pragma unroll
    for (int mf = 0; mf < 2; mf++) {
#pragma unroll
        for (int half = 0; half < 2; half++) {
            const int r = warp_m * 32 + mf * 16 + (lane >> 2) + half * 8;
            if (r < nrows) {
                float* orow = out + (size_t)(row0 + r) * DN;
#pragma unroll
                for (int nf = 0; nf < 8; nf++) {
                    const int col = colBase + nf * 8;
                    float2 v;
                    v.x = acc[mf][nf][half * 2 + 0] + brow[col];
                    v.y = acc[mf][nf][half * 2 + 1] + brow[col + 1];
                    *(float2*)(orow + col) = v;
                }
            }
        }
    }
}

/* ---------------- host launcher ---------------- */
extern "C" void kernel_launch(void* const* d_in, const int* in_sizes, int n_in,
                              void* d_out, int out_size)
{
    const float* x    = (const float*)d_in[0];
    const int*   ef   = (const int*)d_in[1];
    const float* w    = (const float*)d_in[2];
    const float* bias = (const float*)d_in[3];
    float* out = (float*)d_out;

    const long long T = (long long)in_sizes[0] / DK;

    const long long nW4 = (long long)E_NUM * DN * DK / 4;
    cvtW_kernel<<<2368, 256>>>((const float4*)w, nW4);
    build_tiles_kernel<<<1, 32>>>(ef, (int)T);

    cudaFuncSetAttribute(gemm_kernel, cudaFuncAttributeMaxDynamicSharedMemorySize, SMEM_TOTAL);

    const int mt_max = (int)((T + BM - 1) / BM) + E_NUM;   /* ~1056 */
    dim3 grid(DN / BN, (unsigned)mt_max);                  /* (8, ~1056) */
    gemm_kernel<<<grid, 256, SMEM_TOTAL>>>(x, bias, out, (int)T);
}

// round 8
// speedup vs baseline: 1.2513x; 1.2513x over previous
#include <cuda_runtime.h>
#include <cuda_fp16.h>
#include <cstdint>

#define E_NUM 32
#define DK 1024
#define DN 1024
#define BM 128
#define BN 64
#define KC 64            /* fp16 per K-chunk = 128 bytes/row */
#define NCHUNK (DK / KC) /* 16 */
#define STAGES 3
#define MT_CAP 1152
#define TMAX 131072LL

/* ---------------- scratch (device globals; no allocation APIs) -------------- */
static __device__ __align__(1024) __half g_Ah[TMAX * DK];                   /* 256 MB */
static __device__ __align__(1024) __half g_Wh[(long long)E_NUM * DN * DK];  /* 64 MB  */
static __device__ int g_tile_expert[MT_CAP];
static __device__ int g_tile_row[MT_CAP];
static __device__ int g_tile_nrows[MT_CAP];
static __device__ int g_num_mtiles;

/* ---------------- helpers ---------------- */
static __device__ __forceinline__ uint32_t smem_u32(const void* p) {
    uint32_t a;
    asm("{ .reg .u64 t; cvta.to.shared.u64 t, %1; cvt.u32.u64 %0, t; }" : "=r"(a) : "l"(p));
    return a;
}
static __device__ __forceinline__ void cp16(uint32_t dst, const void* src, int src_size) {
    asm volatile("cp.async.cg.shared.global [%0], [%1], 16, %2;\n"
                 :: "r"(dst), "l"(src), "r"(src_size));
}
static __device__ __forceinline__ void cp_async_arrive(uint32_t mbar) {
    asm volatile("cp.async.mbarrier.arrive.noinc.shared.b64 [%0];" :: "r"(mbar) : "memory");
}

#define MBARRIER_INIT(addr, cnt) \
    asm volatile("mbarrier.init.shared.b64 [%0], %1;" :: "r"((uint32_t)(addr)), "r"((uint32_t)(cnt)) : "memory")
#define MBARRIER_ARRIVE(addr) \
    asm volatile("mbarrier.arrive.shared.b64 _, [%0];" :: "r"((uint32_t)(addr)) : "memory")

#define MBARRIER_WAIT_PARITY(mbar_smem_addr, phase_parity) do {                                   \
    uint32_t _mbar = (uint32_t)(mbar_smem_addr);                                                  \
    uint32_t _parity = (uint32_t)(phase_parity);                                                  \
    uint32_t _done;                                                                               \
    asm volatile(                                                                                 \
        "{\n\t"                                                                                   \
        ".reg .pred p;\n\t"                                                                       \
        "mbarrier.try_wait.parity.acquire.cta.shared::cta.b64 p, [%1], %2;\n\t"                   \
        "selp.b32 %0, 1, 0, p;\n\t"                                                               \
        "}"                                                                                       \
        : "=r"(_done) : "r"(_mbar), "r"(_parity) : "memory");                                     \
    if (!_done) {                                                                                 \
        asm volatile(                                                                             \
            "{\n\t"                                                                               \
            ".reg .pred P1;\n\t"                                                                  \
            "WAIT_LOOP_%=:\n\t"                                                                   \
            "mbarrier.try_wait.parity.acquire.cta.shared::cta.b64 P1, [%0], %1, 0x989680;\n\t"    \
            "@P1 bra.uni WAIT_DONE_%=;\n\t"                                                       \
            "bra.uni WAIT_LOOP_%=;\n\t"                                                           \
            "WAIT_DONE_%=:\n\t"                                                                   \
            "}"                                                                                   \
            :: "r"(_mbar), "r"(_parity) : "memory");                                              \
    }                                                                                             \
} while (0)

#define LDSM_X4(r0, r1, r2, r3, addr) \
    asm volatile("ldmatrix.sync.aligned.m8n8.x4.shared.b16 {%0,%1,%2,%3}, [%4];" \
                 : "=r"(r0), "=r"(r1), "=r"(r2), "=r"(r3) : "r"(addr))

#define MMA16816(c0, c1, c2, c3, a0, a1, a2, a3, b0, b1) \
    asm volatile("mma.sync.aligned.m16n8k16.row.col.f32.f16.f16.f32 " \
                 "{%0,%1,%2,%3}, {%4,%5,%6,%7}, {%8,%9}, {%0,%1,%2,%3};" \
                 : "+f"(c0), "+f"(c1), "+f"(c2), "+f"(c3) \
                 : "r"(a0), "r"(a1), "r"(a2), "r"(a3), "r"(b0), "r"(b1))

/* ---------------- fused fp32->fp16 conversion, 16B stores -------------------- */
__global__ void cvt_all_kernel(const float4* __restrict__ srcW,
                               const float4* __restrict__ srcA,
                               long long nW8, long long nA8) {
    long long i = (long long)blockIdx.x * blockDim.x + threadIdx.x;
    long long stride = (long long)gridDim.x * blockDim.x;
    uint4* dstW = reinterpret_cast<uint4*>(g_Wh);
    uint4* dstA = reinterpret_cast<uint4*>(g_Ah);
    const long long ntot = nW8 + nA8;
    for (; i < ntot; i += stride) {
        const bool isW = (i < nW8);
        const long long j = isW ? i : (i - nW8);
        const float4* s = isW ? (srcW + 2 * j) : (srcA + 2 * j);
        float4 v0 = s[0];
        float4 v1 = s[1];
        __half2 h0 = __floats2half2_rn(v0.x, v0.y);
        __half2 h1 = __floats2half2_rn(v0.z, v0.w);
        __half2 h2 = __floats2half2_rn(v1.x, v1.y);
        __half2 h3 = __floats2half2_rn(v1.z, v1.w);
        uint4 u;
        u.x = *reinterpret_cast<uint32_t*>(&h0);
        u.y = *reinterpret_cast<uint32_t*>(&h1);
        u.z = *reinterpret_cast<uint32_t*>(&h2);
        u.w = *reinterpret_cast<uint32_t*>(&h3);
        if (isW) dstW[j] = u; else dstA[j] = u;
    }
}

/* Build tile table. Handles expert_frequency delivered as int32 OR int64. */
__global__ void build_tiles_kernel(const int* __restrict__ ef, int T_tokens) {
    if (threadIdx.x != 0 || blockIdx.x != 0) return;
    long long s = 0;
    for (int i = 0; i < E_NUM; i++) s += ef[i];
    bool is64 = (s != (long long)T_tokens);
    long long off = 0;
    int t = 0;
    for (int e = 0; e < E_NUM; e++) {
        long long c;
        if (is64)
            c = (long long)(unsigned)ef[2 * e] | ((long long)ef[2 * e + 1] << 32);
        else
            c = ef[e];
        for (long long m = 0; m < c; m += BM) {
            long long rem = c - m;
            g_tile_expert[t] = e;
            g_tile_row[t]    = (int)(off + m);
            g_tile_nrows[t]  = (int)(rem < BM ? rem : BM);
            t++;
        }
        off += c;
    }
    g_num_mtiles = t;
}

/* ---------------- main grouped-GEMM kernel (mma.sync fp16) ----------------
   CTA tile 128x64, 8 warps (4m x 2n) -> warp tile 32x32. K-chunk 64,
   3-stage mbarrier full/empty pipeline (R6 protocol), 3 CTAs/SM (24 warps,
   6/SMSP) for latency hiding.
     full[s]:  count 256 (cp.async arrive per thread)
     empty[s]: count 8 (one release per warp)                                 */

#define A_STAGE 16384                   /* 128 rows x 128B */
#define B_STAGE 8192                    /*  64 rows x 128B */
#define STAGE_BYTES (A_STAGE + B_STAGE) /* 24KB */
#define MBAR_BYTES 1024
#define SMEM_TOTAL (STAGES * STAGE_BYTES + MBAR_BYTES)  /* 73KB */

static __device__ __forceinline__ void produce_chunk(
    int cc, uint32_t smem_base, uint32_t mbar_base,
    const __half* __restrict__ gA, const __half* __restrict__ gB,
    int a_sz, int tid, uint32_t* emptyph)
{
    const int s = cc % STAGES;
    if (cc >= STAGES) {
        MBARRIER_WAIT_PARITY(mbar_base + 32 + s * 8, (*emptyph >> s) & 1);
        *emptyph ^= (1u << s);
    }
    /* A: 128 rows, 2 threads/row, 4 x 16B each */
    {
        const int row = tid >> 1;
        const int j0  = (tid & 1) * 4;
        const uint32_t xorv = (uint32_t)(row & 7) * 16u;
        uint32_t dst = smem_base + (uint32_t)s * STAGE_BYTES + (uint32_t)row * 128u;
        const char* src = (const char*)(gA + (size_t)row * DK + (size_t)cc * KC) + j0 * 16;
#pragma unroll
        for (int j = 0; j < 4; j++) {
            uint32_t col = ((uint32_t)(j0 + j) * 16u) ^ xorv;
            cp16(dst + col, src + j * 16, a_sz);
        }
    }
    /* B: 64 rows, 4 threads/row, 2 x 16B each */
    {
        const int row = tid >> 2;
        const int j0  = (tid & 3) * 2;
        const uint32_t xorv = (uint32_t)(row & 7) * 16u;
        uint32_t dst = smem_base + (uint32_t)s * STAGE_BYTES + A_STAGE + (uint32_t)row * 128u;
        const char* src = (const char*)(gB + (size_t)row * DK + (size_t)cc * KC) + j0 * 16;
#pragma unroll
        for (int j = 0; j < 2; j++) {
            uint32_t col = ((uint32_t)(j0 + j) * 16u) ^ xorv;
            cp16(dst + col, src + j * 16, 16);
        }
    }
    cp_async_arrive(mbar_base + s * 8);
}

__global__ void __launch_bounds__(256, 3) gemm_kernel(
    const float* __restrict__ bias, float* __restrict__ out, int T_tokens)
{
    extern __shared__ __align__(1024) char smem[];
    const int nt = blockIdx.x;           /* fast dim: 16 N-tiles share A tile in L2 */
    const int mt = blockIdx.y;
    if (mt >= g_num_mtiles) return;

    const int e     = g_tile_expert[mt];
    const int row0  = g_tile_row[mt];
    const int nrows = g_tile_nrows[mt];

    const uint32_t smem_base = smem_u32(smem);
    const uint32_t mbar_base = smem_base + STAGES * STAGE_BYTES;
    const int tid  = threadIdx.x;
    const int lane = tid & 31;
    const int wid  = tid >> 5;
    const int warp_m = wid >> 1;         /* 0..3 -> 32 rows each */
    const int warp_n = wid & 1;          /* 0..1 -> 32 cols each */

    if (tid == 0) {
#pragma unroll
        for (int s = 0; s < STAGES; s++) {
            MBARRIER_INIT(mbar_base + s * 8, 256);       /* full  */
            MBARRIER_INIT(mbar_base + 32 + s * 8, 8);    /* empty */
        }
    }
    __syncthreads();

    /* global load setup */
    const int arow = tid >> 1;
    const int a_sz = (row0 + arow < T_tokens) ? 16 : 0;
    const __half* gA = g_Ah + (size_t)row0 * DK;
    const __half* gB = g_Wh + ((size_t)e * DN + (size_t)nt * BN) * DK;

    /* ldmatrix per-lane address components */
    uint32_t aRow[2], aXor[2];
#pragma unroll
    for (int mf = 0; mf < 2; mf++) {
        int r = warp_m * 32 + mf * 16 + (lane & 15);
        aRow[mf] = (uint32_t)r * 128u;
        aXor[mf] = (uint32_t)(r & 7) * 16u;
    }
    const uint32_t aHi = (uint32_t)((lane >> 4) & 1) * 16u;

    uint32_t bRow[2], bXor[2];
#pragma unroll
    for (int g = 0; g < 2; g++) {
        int r = warp_n * 32 + g * 16 + (lane & 7) + (((lane >> 4) & 1) << 3);
        bRow[g] = (uint32_t)r * 128u;
        bXor[g] = (uint32_t)(r & 7) * 16u;
    }
    const uint32_t bHi = (uint32_t)((lane >> 3) & 1) * 16u;

    float acc[2][4][4];
#pragma unroll
    for (int mf = 0; mf < 2; mf++)
#pragma unroll
        for (int nf = 0; nf < 4; nf++)
#pragma unroll
            for (int k = 0; k < 4; k++) acc[mf][nf][k] = 0.0f;

    uint32_t fullph = 0, emptyph = 0;

    /* prologue: chunks 0 and 1 */
    produce_chunk(0, smem_base, mbar_base, gA, gB, a_sz, tid, &emptyph);
    produce_chunk(1, smem_base, mbar_base, gA, gB, a_sz, tid, &emptyph);

#pragma unroll 1
    for (int c = 0; c < NCHUNK; c++) {
        const int s = c % STAGES;

        if (c + 2 < NCHUNK)
            produce_chunk(c + 2, smem_base, mbar_base, gA, gB, a_sz, tid, &emptyph);

        MBARRIER_WAIT_PARITY(mbar_base + s * 8, (fullph >> s) & 1);
        fullph ^= (1u << s);

        const uint32_t sA = smem_base + (uint32_t)s * STAGE_BYTES;
        const uint32_t sB = sA + A_STAGE;

#pragma unroll
        for (int ks = 0; ks < 4; ks++) {
            const uint32_t kb = (uint32_t)ks * 32u;
            uint32_t a[2][4];
#pragma unroll
            for (int mf = 0; mf < 2; mf++) {
                uint32_t addr = sA + aRow[mf] + ((kb + aHi) ^ aXor[mf]);
                LDSM_X4(a[mf][0], a[mf][1], a[mf][2], a[mf][3], addr);
            }
            uint32_t b[2][4];
#pragma unroll
            for (int g = 0; g < 2; g++) {
                uint32_t addr = sB + bRow[g] + ((kb + bHi) ^ bXor[g]);
                LDSM_X4(b[g][0], b[g][1], b[g][2], b[g][3], addr);
            }
#pragma unroll
            for (int mf = 0; mf < 2; mf++) {
#pragma unroll
                for (int nf = 0; nf < 4; nf++) {
                    const int g  = nf >> 1;
                    const int hi = (nf & 1) * 2;
                    MMA16816(acc[mf][nf][0], acc[mf][nf][1], acc[mf][nf][2], acc[mf][nf][3],
                             a[mf][0], a[mf][1], a[mf][2], a[mf][3],
                             b[g][hi], b[g][hi + 1]);
                }
            }
        }

        if (lane == 0) MBARRIER_ARRIVE(mbar_base + 32 + s * 8);
    }

    /* epilogue: out = acc + bias */
    const int colBase = nt * BN + warp_n * 32 + (lane & 3) * 2;
    const float* brow = bias + (size_t)e * DN;
#pragma unroll
    for (int mf = 0; mf < 2; mf++) {
#pragma unroll
        for (int half = 0; half < 2; half++) {
            const int r = warp_m * 32 + mf * 16 + (lane >> 2) + half * 8;
            if (r < nrows) {
                float* orow = out + (size_t)(row0 + r) * DN;
#pragma unroll
                for (int nf = 0; nf < 4; nf++) {
                    const int col = colBase + nf * 8;
                    float2 v;
                    v.x = acc[mf][nf][half * 2 + 0] + brow[col];
                    v.y = acc[mf][nf][half * 2 + 1] + brow[col + 1];
                    *(float2*)(orow + col) = v;
                }
            }
        }
    }
}

/* ---------------- host launcher ---------------- */
extern "C" void kernel_launch(void* const* d_in, const int* in_sizes, int n_in,
                              void* d_out, int out_size)
{
    const float* x    = (const float*)d_in[0];
    const int*   ef   = (const int*)d_in[1];
    const float* w    = (const float*)d_in[2];
    const float* bias = (const float*)d_in[3];
    float* out = (float*)d_out;

    const long long T = (long long)in_sizes[0] / DK;

    const long long nA8 = T * DK / 8;
    const long long nW8 = (long long)E_NUM * DN * DK / 8;
    cvt_all_kernel<<<4736, 256>>>((const float4*)w, (const float4*)x, nW8, nA8);
    build_tiles_kernel<<<1, 32>>>(ef, (int)T);

    cudaFuncSetAttribute(gemm_kernel, cudaFuncAttributeMaxDynamicSharedMemorySize, SMEM_TOTAL);

    const int mt_max = (int)((T + BM - 1) / BM) + E_NUM;   /* ~1056 */
    dim3 grid(DN / BN, (unsigned)mt_max);                  /* (16, ~1056) */
    gemm_kernel<<<grid, 256, SMEM_TOTAL>>>(bias, out, (int)T);
}

// round 9
// speedup vs baseline: 1.3480x; 1.0772x over previous
#include <cuda_runtime.h>
#include <cuda_fp16.h>
#include <cstdint>

#define E_NUM 32
#define DK 1024
#define DN 1024
#define BM 128
#define BN 128
#define KC 64            /* fp16 per K-chunk = 128 bytes/row */
#define NCHUNK (DK / KC) /* 16 */
#define STAGES 3
#define MT_CAP 1152
#define TMAX 131072LL

/* ---------------- scratch (device globals; no allocation APIs) -------------- */
static __device__ __align__(1024) __half g_Ah[TMAX * DK];                   /* 256 MB */
static __device__ __align__(1024) __half g_Wh[(long long)E_NUM * DN * DK];  /* 64 MB  */
static __device__ int g_tile_expert[MT_CAP];
static __device__ int g_tile_row[MT_CAP];
static __device__ int g_tile_nrows[MT_CAP];
static __device__ int g_num_mtiles;

/* ---------------- helpers ---------------- */
static __device__ __forceinline__ uint32_t smem_u32(const void* p) {
    uint32_t a;
    asm("{ .reg .u64 t; cvta.to.shared.u64 t, %1; cvt.u32.u64 %0, t; }" : "=r"(a) : "l"(p));
    return a;
}
static __device__ __forceinline__ void cp16(uint32_t dst, const void* src, int src_size) {
    asm volatile("cp.async.cg.shared.global [%0], [%1], 16, %2;\n"
                 :: "r"(dst), "l"(src), "r"(src_size));
}
static __device__ __forceinline__ void cp_async_arrive(uint32_t mbar) {
    asm volatile("cp.async.mbarrier.arrive.noinc.shared.b64 [%0];" :: "r"(mbar) : "memory");
}

#define MBARRIER_INIT(addr, cnt) \
    asm volatile("mbarrier.init.shared.b64 [%0], %1;" :: "r"((uint32_t)(addr)), "r"((uint32_t)(cnt)) : "memory")
#define MBARRIER_ARRIVE(addr) \
    asm volatile("mbarrier.arrive.shared.b64 _, [%0];" :: "r"((uint32_t)(addr)) : "memory")

#define MBARRIER_WAIT_PARITY(mbar_smem_addr, phase_parity) do {                                   \
    uint32_t _mbar = (uint32_t)(mbar_smem_addr);                                                  \
    uint32_t _parity = (uint32_t)(phase_parity);                                                  \
    uint32_t _done;                                                                               \
    asm volatile(                                                                                 \
        "{\n\t"                                                                                   \
        ".reg .pred p;\n\t"                                                                       \
        "mbarrier.try_wait.parity.acquire.cta.shared::cta.b64 p, [%1], %2;\n\t"                   \
        "selp.b32 %0, 1, 0, p;\n\t"                                                               \
        "}"                                                                                       \
        : "=r"(_done) : "r"(_mbar), "r"(_parity) : "memory");                                     \
    if (!_done) {                                                                                 \
        asm volatile(                                                                             \
            "{\n\t"                                                                               \
            ".reg .pred P1;\n\t"                                                                  \
            "WAIT_LOOP_%=:\n\t"                                                                   \
            "mbarrier.try_wait.parity.acquire.cta.shared::cta.b64 P1, [%0], %1, 0x989680;\n\t"    \
            "@P1 bra.uni WAIT_DONE_%=;\n\t"                                                       \
            "bra.uni WAIT_LOOP_%=;\n\t"                                                           \
            "WAIT_DONE_%=:\n\t"                                                                   \
            "}"                                                                                   \
            :: "r"(_mbar), "r"(_parity) : "memory");                                              \
    }                                                                                             \
} while (0)

#define LDSM_X4(r0, r1, r2, r3, addr) \
    asm volatile("ldmatrix.sync.aligned.m8n8.x4.shared.b16 {%0,%1,%2,%3}, [%4];" \
                 : "=r"(r0), "=r"(r1), "=r"(r2), "=r"(r3) : "r"(addr))

#define MMA16816(c0, c1, c2, c3, a0, a1, a2, a3, b0, b1) \
    asm volatile("mma.sync.aligned.m16n8k16.row.col.f32.f16.f16.f32 " \
                 "{%0,%1,%2,%3}, {%4,%5,%6,%7}, {%8,%9}, {%0,%1,%2,%3};" \
                 : "+f"(c0), "+f"(c1), "+f"(c2), "+f"(c3) \
                 : "r"(a0), "r"(a1), "r"(a2), "r"(a3), "r"(b0), "r"(b1))

/* -------- fused fp32->fp16 conversion: 32B per thread-iter (2x uint4) -------- */
__global__ void cvt_all_kernel(const float4* __restrict__ srcW,
                               const float4* __restrict__ srcA,
                               long long nW16, long long nA16) {
    long long i = (long long)blockIdx.x * blockDim.x + threadIdx.x;
    long long stride = (long long)gridDim.x * blockDim.x;
    uint4* dstW = reinterpret_cast<uint4*>(g_Wh);
    uint4* dstA = reinterpret_cast<uint4*>(g_Ah);
    const long long ntot = nW16 + nA16;
    for (; i < ntot; i += stride) {
        const bool isW = (i < nW16);
        const long long j = isW ? i : (i - nW16);
        const float4* s = isW ? (srcW + 4 * j) : (srcA + 4 * j);
        /* two independent 16B-output units -> 4 loads in flight */
        float4 v0 = s[0];
        float4 v1 = s[1];
        float4 v2 = s[2];
        float4 v3 = s[3];
        __half2 h;
        uint4 u0, u1;
        h = __floats2half2_rn(v0.x, v0.y); u0.x = *(uint32_t*)&h;
        h = __floats2half2_rn(v0.z, v0.w); u0.y = *(uint32_t*)&h;
        h = __floats2half2_rn(v1.x, v1.y); u0.z = *(uint32_t*)&h;
        h = __floats2half2_rn(v1.z, v1.w); u0.w = *(uint32_t*)&h;
        h = __floats2half2_rn(v2.x, v2.y); u1.x = *(uint32_t*)&h;
        h = __floats2half2_rn(v2.z, v2.w); u1.y = *(uint32_t*)&h;
        h = __floats2half2_rn(v3.x, v3.y); u1.z = *(uint32_t*)&h;
        h = __floats2half2_rn(v3.z, v3.w); u1.w = *(uint32_t*)&h;
        if (isW) { dstW[2 * j] = u0; dstW[2 * j + 1] = u1; }
        else     { dstA[2 * j] = u0; dstA[2 * j + 1] = u1; }
    }
}

/* Build tile table. Handles expert_frequency delivered as int32 OR int64. */
__global__ void build_tiles_kernel(const int* __restrict__ ef, int T_tokens) {
    if (threadIdx.x != 0 || blockIdx.x != 0) return;
    long long s = 0;
    for (int i = 0; i < E_NUM; i++) s += ef[i];
    bool is64 = (s != (long long)T_tokens);
    long long off = 0;
    int t = 0;
    for (int e = 0; e < E_NUM; e++) {
        long long c;
        if (is64)
            c = (long long)(unsigned)ef[2 * e] | ((long long)ef[2 * e + 1] << 32);
        else
            c = ef[e];
        for (long long m = 0; m < c; m += BM) {
            long long rem = c - m;
            g_tile_expert[t] = e;
            g_tile_row[t]    = (int)(off + m);
            g_tile_nrows[t]  = (int)(rem < BM ? rem : BM);
            t++;
        }
        off += c;
    }
    g_num_mtiles = t;
}

/* ---------------- main grouped-GEMM kernel (mma.sync fp16) ----------------
   R6 config verbatim: CTA 128x128, 8 warps (4m x 2n), warp 32x64, K-chunk
   64, 3-stage mbarrier full/empty pipeline, 2 CTAs/SM.
     full[s]:  count 256 (cp.async arrive per thread)
     empty[s]: count 8 (one release per warp after its LDSMs)                 */

#define STAGE_BYTES 32768              /* A 16KB + B 16KB */
#define MBAR_BYTES  1024
#define SMEM_TOTAL  (STAGES * STAGE_BYTES + MBAR_BYTES)
/* mbar layout: full[s] at +s*8; empty[s] at +32+s*8 */

static __device__ __forceinline__ void produce_chunk(
    int cc, uint32_t smem_base, uint32_t mbar_base,
    const __half* __restrict__ gA, const __half* __restrict__ gB,
    int a_sz, int tid, uint32_t* emptyph)
{
    const int s = cc % STAGES;
    if (cc >= STAGES) {   /* first use of each stage needs no empty-wait */
        MBARRIER_WAIT_PARITY(mbar_base + 32 + s * 8, (*emptyph >> s) & 1);
        *emptyph ^= (1u << s);
    }
    const int row  = tid >> 1;
    const int j0   = (tid & 1) * 4;
    const uint32_t xorv = (uint32_t)(row & 7) * 16u;
    uint32_t sA = smem_base + (uint32_t)s * STAGE_BYTES + (uint32_t)row * 128u;
    uint32_t sB = sA + 16384u;
    const char* srcA = (const char*)(gA + (size_t)row * DK + (size_t)cc * KC) + j0 * 16;
    const char* srcB = (const char*)(gB + (size_t)row * DK + (size_t)cc * KC) + j0 * 16;
#pragma unroll
    for (int j = 0; j < 4; j++) {
        uint32_t col = ((uint32_t)(j0 + j) * 16u) ^ xorv;
        cp16(sA + col, srcA + j * 16, a_sz);
        cp16(sB + col, srcB + j * 16, 16);
    }
    cp_async_arrive(mbar_base + s * 8);
}

__global__ void __launch_bounds__(256, 2) gemm_kernel(
    const float* __restrict__ bias, float* __restrict__ out, int T_tokens)
{
    extern __shared__ __align__(1024) char smem[];
    const int nt = blockIdx.x;           /* fast dim: 8 N-tiles share A tile in L2 */
    const int mt = blockIdx.y;
    if (mt >= g_num_mtiles) return;

    const int e     = g_tile_expert[mt];
    const int row0  = g_tile_row[mt];
    const int nrows = g_tile_nrows[mt];

    const uint32_t smem_base = smem_u32(smem);
    const uint32_t mbar_base = smem_base + STAGES * STAGE_BYTES;
    const int tid  = threadIdx.x;
    const int lane = tid & 31;
    const int wid  = tid >> 5;
    const int warp_m = wid >> 1;         /* 0..3 */
    const int warp_n = wid & 1;          /* 0..1 */

    if (tid == 0) {
#pragma unroll
        for (int s = 0; s < STAGES; s++) {
            MBARRIER_INIT(mbar_base + s * 8, 256);       /* full  */
            MBARRIER_INIT(mbar_base + 32 + s * 8, 8);    /* empty */
        }
    }
    __syncthreads();

    /* global load setup */
    const int arow = tid >> 1;
    const int a_sz = (row0 + arow < T_tokens) ? 16 : 0;
    const __half* gA = g_Ah + (size_t)row0 * DK;
    const __half* gB = g_Wh + ((size_t)e * DN + (size_t)nt * BN) * DK;

    /* ldmatrix per-lane address components */
    uint32_t aRow[2], aXor[2];
#pragma unroll
    for (int mf = 0; mf < 2; mf++) {
        int r = warp_m * 32 + mf * 16 + (lane & 15);
        aRow[mf] = (uint32_t)r * 128u;
        aXor[mf] = (uint32_t)(r & 7) * 16u;
    }
    const uint32_t aHi = (uint32_t)((lane >> 4) & 1) * 16u;

    uint32_t bRow[4], bXor[4];
#pragma unroll
    for (int g = 0; g < 4; g++) {
        int r = warp_n * 64 + g * 16 + (lane & 7) + (((lane >> 4) & 1) << 3);
        bRow[g] = (uint32_t)r * 128u;
        bXor[g] = (uint32_t)(r & 7) * 16u;
    }
    const uint32_t bHi = (uint32_t)((lane >> 3) & 1) * 16u;

    float acc[2][8][4];
#pragma unroll
    for (int mf = 0; mf < 2; mf++)
#pragma unroll
        for (int nf = 0; nf < 8; nf++)
#pragma unroll
            for (int k = 0; k < 4; k++) acc[mf][nf][k] = 0.0f;

    uint32_t fullph = 0, emptyph = 0;

    /* prologue: chunks 0 and 1 (no waits: first use of stages 0,1) */
    produce_chunk(0, smem_base, mbar_base, gA, gB, a_sz, tid, &emptyph);
    produce_chunk(1, smem_base, mbar_base, gA, gB, a_sz, tid, &emptyph);

#pragma unroll 1
    for (int c = 0; c < NCHUNK; c++) {
        const int s = c % STAGES;

        /* produce chunk c+2 (its stage was consumed at chunk c-1) */
        if (c + 2 < NCHUNK)
            produce_chunk(c + 2, smem_base, mbar_base, gA, gB, a_sz, tid, &emptyph);

        /* consume chunk c: per-warp wait on full[s] */
        MBARRIER_WAIT_PARITY(mbar_base + s * 8, (fullph >> s) & 1);
        fullph ^= (1u << s);

        const uint32_t sA = smem_base + (uint32_t)s * STAGE_BYTES;
        const uint32_t sB = sA + 16384u;

#pragma unroll
        for (int ks = 0; ks < 4; ks++) {
            const uint32_t kb = (uint32_t)ks * 32u;
            uint32_t a[2][4];
#pragma unroll
            for (int mf = 0; mf < 2; mf++) {
                uint32_t addr = sA + aRow[mf] + ((kb + aHi) ^ aXor[mf]);
                LDSM_X4(a[mf][0], a[mf][1], a[mf][2], a[mf][3], addr);
            }
            uint32_t b[4][4];
#pragma unroll
            for (int g = 0; g < 4; g++) {
                uint32_t addr = sB + bRow[g] + ((kb + bHi) ^ bXor[g]);
                LDSM_X4(b[g][0], b[g][1], b[g][2], b[g][3], addr);
            }
#pragma unroll
            for (int mf = 0; mf < 2; mf++) {
#pragma unroll
                for (int nf = 0; nf < 8; nf++) {
                    const int g  = nf >> 1;
                    const int hi = (nf & 1) * 2;
                    MMA16816(acc[mf][nf][0], acc[mf][nf][1], acc[mf][nf][2], acc[mf][nf][3],
                             a[mf][0], a[mf][1], a[mf][2], a[mf][3],
                             b[g][hi], b[g][hi + 1]);
                }
            }
        }

        /* this warp is done reading stage s */
        if (lane == 0) MBARRIER_ARRIVE(mbar_base + 32 + s * 8);
    }

    /* epilogue: out = acc + bias */
    const int colBase = nt * BN + warp_n * 64 + (lane & 3) * 2;
    const float* brow = bias + (size_t)e * DN;
#pragma unroll
    for (int mf = 0; mf < 2; mf++) {
#pragma unroll
        for (int half = 0; half < 2; half++) {
            const int r = warp_m * 32 + mf * 16 + (lane >> 2) + half * 8;
            if (r < nrows) {
                float* orow = out + (size_t)(row0 + r) * DN;
#pragma unroll
                for (int nf = 0; nf < 8; nf++) {
                    const int col = colBase + nf * 8;
                    float2 v;
                    v.x = acc[mf][nf][half * 2 + 0] + brow[col];
                    v.y = acc[mf][nf][half * 2 + 1] + brow[col + 1];
                    *(float2*)(orow + col) = v;
                }
            }
        }
    }
}

/* ---------------- host launcher ---------------- */
extern "C" void kernel_launch(void* const* d_in, const int* in_sizes, int n_in,
                              void* d_out, int out_size)
{
    const float* x    = (const float*)d_in[0];
    const int*   ef   = (const int*)d_in[1];
    const float* w    = (const float*)d_in[2];
    const float* bias = (const float*)d_in[3];
    float* out = (float*)d_out;

    const long long T = (long long)in_sizes[0] / DK;

    const long long nA16 = T * DK / 16;
    const long long nW16 = (long long)E_NUM * DN * DK / 16;
    cvt_all_kernel<<<4736, 256>>>((const float4*)w, (const float4*)x, nW16, nA16);
    build_tiles_kernel<<<1, 32>>>(ef, (int)T);

    cudaFuncSetAttribute(gemm_kernel, cudaFuncAttributeMaxDynamicSharedMemorySize, SMEM_TOTAL);

    const int mt_max = (int)((T + BM - 1) / BM) + E_NUM;   /* ~1056 */
    dim3 grid(DN / BN, (unsigned)mt_max);                  /* (8, ~1056) */
    gemm_kernel<<<grid, 256, SMEM_TOTAL>>>(bias, out, (int)T);
}

// round 10
// speedup vs baseline: 1.3543x; 1.0047x over previous
#include <cuda_runtime.h>
#include <cuda_fp16.h>
#include <cstdint>

#define E_NUM 32
#define DK 1024
#define DN 1024
#define BM 128
#define BN 128
#define KC 64            /* fp16 per K-chunk = 128 bytes/row */
#define NCHUNK (DK / KC) /* 16 */
#define STAGES 3
#define MT_CAP 1152
#define TMAX 131072LL

/* ---------------- scratch (device globals; no allocation APIs) -------------- */
static __device__ __align__(1024) __half g_Ah[TMAX * DK];                   /* 256 MB */
static __device__ __align__(1024) __half g_Wh[(long long)E_NUM * DN * DK];  /* 64 MB  */
static __device__ int g_tile_expert[MT_CAP];
static __device__ int g_tile_row[MT_CAP];
static __device__ int g_tile_nrows[MT_CAP];
static __device__ int g_num_mtiles;

/* ---------------- helpers ---------------- */
static __device__ __forceinline__ uint32_t smem_u32(const void* p) {
    uint32_t a;
    asm("{ .reg .u64 t; cvta.to.shared.u64 t, %1; cvt.u32.u64 %0, t; }" : "=r"(a) : "l"(p));
    return a;
}
static __device__ __forceinline__ void cp16(uint32_t dst, const void* src, int src_size) {
    asm volatile("cp.async.cg.shared.global [%0], [%1], 16, %2;\n"
                 :: "r"(dst), "l"(src), "r"(src_size));
}
static __device__ __forceinline__ void cp_async_arrive(uint32_t mbar) {
    asm volatile("cp.async.mbarrier.arrive.noinc.shared.b64 [%0];" :: "r"(mbar) : "memory");
}

#define MBARRIER_INIT(addr, cnt) \
    asm volatile("mbarrier.init.shared.b64 [%0], %1;" :: "r"((uint32_t)(addr)), "r"((uint32_t)(cnt)) : "memory")
#define MBARRIER_ARRIVE(addr) \
    asm volatile("mbarrier.arrive.shared.b64 _, [%0];" :: "r"((uint32_t)(addr)) : "memory")

/* acquire wait: consumer side (generic-proxy LDS reads follow) */
#define MBARRIER_WAIT_PARITY(mbar_smem_addr, phase_parity) do {                                   \
    uint32_t _mbar = (uint32_t)(mbar_smem_addr);                                                  \
    uint32_t _parity = (uint32_t)(phase_parity);                                                  \
    uint32_t _done;                                                                               \
    asm volatile(                                                                                 \
        "{\n\t"                                                                                   \
        ".reg .pred p;\n\t"                                                                       \
        "mbarrier.try_wait.parity.acquire.cta.shared::cta.b64 p, [%1], %2;\n\t"                   \
        "selp.b32 %0, 1, 0, p;\n\t"                                                               \
        "}"                                                                                       \
        : "=r"(_done) : "r"(_mbar), "r"(_parity) : "memory");                                     \
    if (!_done) {                                                                                 \
        asm volatile(                                                                             \
            "{\n\t"                                                                               \
            ".reg .pred P1;\n\t"                                                                  \
            "WAIT_LOOP_%=:\n\t"                                                                   \
            "mbarrier.try_wait.parity.acquire.cta.shared::cta.b64 P1, [%0], %1, 0x989680;\n\t"    \
            "@P1 bra.uni WAIT_DONE_%=;\n\t"                                                       \
            "bra.uni WAIT_LOOP_%=;\n\t"                                                           \
            "WAIT_DONE_%=:\n\t"                                                                   \
            "}"                                                                                   \
            :: "r"(_mbar), "r"(_parity) : "memory");                                              \
    }                                                                                             \
} while (0)

/* relaxed wait: producer side (only async-proxy cp.async writes follow) */
#define MBARRIER_WAIT_PARITY_RELAXED(mbar_smem_addr, phase_parity) do {                           \
    uint32_t _mbar = (uint32_t)(mbar_smem_addr);                                                  \
    uint32_t _parity = (uint32_t)(phase_parity);                                                  \
    uint32_t _done;                                                                               \
    asm volatile(                                                                                 \
        "{\n\t"                                                                                   \
        ".reg .pred p;\n\t"                                                                       \
        "mbarrier.try_wait.parity.relaxed.cta.shared::cta.b64 p, [%1], %2;\n\t"                   \
        "selp.b32 %0, 1, 0, p;\n\t"                                                               \
        "}"                                                                                       \
        : "=r"(_done) : "r"(_mbar), "r"(_parity) : "memory");                                     \
    if (!_done) {                                                                                 \
        asm volatile(                                                                             \
            "{\n\t"                                                                               \
            ".reg .pred P1;\n\t"                                                                  \
            "WAIT_LOOP_%=:\n\t"                                                                   \
            "mbarrier.try_wait.parity.relaxed.cta.shared::cta.b64 P1, [%0], %1, 0x989680;\n\t"    \
            "@P1 bra.uni WAIT_DONE_%=;\n\t"                                                       \
            "bra.uni WAIT_LOOP_%=;\n\t"                                                           \
            "WAIT_DONE_%=:\n\t"                                                                   \
            "}"                                                                                   \
            :: "r"(_mbar), "r"(_parity) : "memory");                                              \
    }                                                                                             \
} while (0)

#define LDSM_X4(r0, r1, r2, r3, addr) \
    asm volatile("ldmatrix.sync.aligned.m8n8.x4.shared.b16 {%0,%1,%2,%3}, [%4];" \
                 : "=r"(r0), "=r"(r1), "=r"(r2), "=r"(r3) : "r"(addr))

#define MMA16816(c0, c1, c2, c3, a0, a1, a2, a3, b0, b1) \
    asm volatile("mma.sync.aligned.m16n8k16.row.col.f32.f16.f16.f32 " \
                 "{%0,%1,%2,%3}, {%4,%5,%6,%7}, {%8,%9}, {%0,%1,%2,%3};" \
                 : "+f"(c0), "+f"(c1), "+f"(c2), "+f"(c3) \
                 : "r"(a0), "r"(a1), "r"(a2), "r"(a3), "r"(b0), "r"(b1))

/* -------- fused fp32->fp16 conversion: 32B per thread-iter (2x uint4) -------- */
__global__ void cvt_all_kernel(const float4* __restrict__ srcW,
                               const float4* __restrict__ srcA,
                               long long nW16, long long nA16) {
    long long i = (long long)blockIdx.x * blockDim.x + threadIdx.x;
    long long stride = (long long)gridDim.x * blockDim.x;
    uint4* dstW = reinterpret_cast<uint4*>(g_Wh);
    uint4* dstA = reinterpret_cast<uint4*>(g_Ah);
    const long long ntot = nW16 + nA16;
    for (; i < ntot; i += stride) {
        const bool isW = (i < nW16);
        const long long j = isW ? i : (i - nW16);
        const float4* s = isW ? (srcW + 4 * j) : (srcA + 4 * j);
        float4 v0 = s[0];
        float4 v1 = s[1];
        float4 v2 = s[2];
        float4 v3 = s[3];
        __half2 h;
        uint4 u0, u1;
        h = __floats2half2_rn(v0.x, v0.y); u0.x = *(uint32_t*)&h;
        h = __floats2half2_rn(v0.z, v0.w); u0.y = *(uint32_t*)&h;
        h = __floats2half2_rn(v1.x, v1.y); u0.z = *(uint32_t*)&h;
        h = __floats2half2_rn(v1.z, v1.w); u0.w = *(uint32_t*)&h;
        h = __floats2half2_rn(v2.x, v2.y); u1.x = *(uint32_t*)&h;
        h = __floats2half2_rn(v2.z, v2.w); u1.y = *(uint32_t*)&h;
        h = __floats2half2_rn(v3.x, v3.y); u1.z = *(uint32_t*)&h;
        h = __floats2half2_rn(v3.z, v3.w); u1.w = *(uint32_t*)&h;
        if (isW) { dstW[2 * j] = u0; dstW[2 * j + 1] = u1; }
        else     { dstA[2 * j] = u0; dstA[2 * j + 1] = u1; }
    }
}

/* Build tile table. Handles expert_frequency delivered as int32 OR int64. */
__global__ void build_tiles_kernel(const int* __restrict__ ef, int T_tokens) {
    if (threadIdx.x != 0 || blockIdx.x != 0) return;
    long long s = 0;
    for (int i = 0; i < E_NUM; i++) s += ef[i];
    bool is64 = (s != (long long)T_tokens);
    long long off = 0;
    int t = 0;
    for (int e = 0; e < E_NUM; e++) {
        long long c;
        if (is64)
            c = (long long)(unsigned)ef[2 * e] | ((long long)ef[2 * e + 1] << 32);
        else
            c = ef[e];
        for (long long m = 0; m < c; m += BM) {
            long long rem = c - m;
            g_tile_expert[t] = e;
            g_tile_row[t]    = (int)(off + m);
            g_tile_nrows[t]  = (int)(rem < BM ? rem : BM);
            t++;
        }
        off += c;
    }
    g_num_mtiles = t;
}

/* ---------------- main grouped-GEMM kernel (mma.sync fp16) ----------------
   R6 config: CTA 128x128, 8 warps (4m x 2n), warp 32x64, K-chunk 64,
   3-stage mbarrier full/empty pipeline, 2 CTAs/SM.
   NEW vs R9: (1) empty-arrive moved to right after the last ks's LDSMs
   (the only SMEM readers) instead of after its MMAs; (2) producer empty-
   wait uses relaxed semantics (only async-proxy writes follow).              */

#define STAGE_BYTES 32768              /* A 16KB + B 16KB */
#define MBAR_BYTES  1024
#define SMEM_TOTAL  (STAGES * STAGE_BYTES + MBAR_BYTES)
/* mbar layout: full[s] at +s*8; empty[s] at +32+s*8 */

static __device__ __forceinline__ void produce_chunk(
    int cc, uint32_t smem_base, uint32_t mbar_base,
    const __half* __restrict__ gA, const __half* __restrict__ gB,
    int a_sz, int tid, uint32_t* emptyph)
{
    const int s = cc % STAGES;
    if (cc >= STAGES) {   /* first use of each stage needs no empty-wait */
        MBARRIER_WAIT_PARITY_RELAXED(mbar_base + 32 + s * 8, (*emptyph >> s) & 1);
        *emptyph ^= (1u << s);
    }
    const int row  = tid >> 1;
    const int j0   = (tid & 1) * 4;
    const uint32_t xorv = (uint32_t)(row & 7) * 16u;
    uint32_t sA = smem_base + (uint32_t)s * STAGE_BYTES + (uint32_t)row * 128u;
    uint32_t sB = sA + 16384u;
    const char* srcA = (const char*)(gA + (size_t)row * DK + (size_t)cc * KC) + j0 * 16;
    const char* srcB = (const char*)(gB + (size_t)row * DK + (size_t)cc * KC) + j0 * 16;
#pragma unroll
    for (int j = 0; j < 4; j++) {
        uint32_t col = ((uint32_t)(j0 + j) * 16u) ^ xorv;
        cp16(sA + col, srcA + j * 16, a_sz);
        cp16(sB + col, srcB + j * 16, 16);
    }
    cp_async_arrive(mbar_base + s * 8);
}

__global__ void __launch_bounds__(256, 2) gemm_kernel(
    const float* __restrict__ bias, float* __restrict__ out, int T_tokens)
{
    extern __shared__ __align__(1024) char smem[];
    const int nt = blockIdx.x;           /* fast dim: 8 N-tiles share A tile in L2 */
    const int mt = blockIdx.y;
    if (mt >= g_num_mtiles) return;

    const int e     = g_tile_expert[mt];
    const int row0  = g_tile_row[mt];
    const int nrows = g_tile_nrows[mt];

    const uint32_t smem_base = smem_u32(smem);
    const uint32_t mbar_base = smem_base + STAGES * STAGE_BYTES;
    const int tid  = threadIdx.x;
    const int lane = tid & 31;
    const int wid  = tid >> 5;
    const int warp_m = wid >> 1;         /* 0..3 */
    const int warp_n = wid & 1;          /* 0..1 */

    if (tid == 0) {
#pragma unroll
        for (int s = 0; s < STAGES; s++) {
            MBARRIER_INIT(mbar_base + s * 8, 256);       /* full  */
            MBARRIER_INIT(mbar_base + 32 + s * 8, 8);    /* empty */
        }
    }
    __syncthreads();

    /* global load setup */
    const int arow = tid >> 1;
    const int a_sz = (row0 + arow < T_tokens) ? 16 : 0;
    const __half* gA = g_Ah + (size_t)row0 * DK;
    const __half* gB = g_Wh + ((size_t)e * DN + (size_t)nt * BN) * DK;

    /* ldmatrix per-lane address components */
    uint32_t aRow[2], aXor[2];
#pragma unroll
    for (int mf = 0; mf < 2; mf++) {
        int r = warp_m * 32 + mf * 16 + (lane & 15);
        aRow[mf] = (uint32_t)r * 128u;
        aXor[mf] = (uint32_t)(r & 7) * 16u;
    }
    const uint32_t aHi = (uint32_t)((lane >> 4) & 1) * 16u;

    uint32_t bRow[4], bXor[4];
#pragma unroll
    for (int g = 0; g < 4; g++) {
        int r = warp_n * 64 + g * 16 + (lane & 7) + (((lane >> 4) & 1) << 3);
        bRow[g] = (uint32_t)r * 128u;
        bXor[g] = (uint32_t)(r & 7) * 16u;
    }
    const uint32_t bHi = (uint32_t)((lane >> 3) & 1) * 16u;

    float acc[2][8][4];
#pragma unroll
    for (int mf = 0; mf < 2; mf++)
#pragma unroll
        for (int nf = 0; nf < 8; nf++)
#pragma unroll
            for (int k = 0; k < 4; k++) acc[mf][nf][k] = 0.0f;

    uint32_t fullph = 0, emptyph = 0;

    /* prologue: chunks 0 and 1 (no waits: first use of stages 0,1) */
    produce_chunk(0, smem_base, mbar_base, gA, gB, a_sz, tid, &emptyph);
    produce_chunk(1, smem_base, mbar_base, gA, gB, a_sz, tid, &emptyph);

#pragma unroll 1
    for (int c = 0; c < NCHUNK; c++) {
        const int s = c % STAGES;

        /* produce chunk c+2 (its stage was released during chunk c-1) */
        if (c + 2 < NCHUNK)
            produce_chunk(c + 2, smem_base, mbar_base, gA, gB, a_sz, tid, &emptyph);

        /* consume chunk c: per-warp wait on full[s] */
        MBARRIER_WAIT_PARITY(mbar_base + s * 8, (fullph >> s) & 1);
        fullph ^= (1u << s);

        const uint32_t sA = smem_base + (uint32_t)s * STAGE_BYTES;
        const uint32_t sB = sA + 16384u;

#pragma unroll
        for (int ks = 0; ks < 4; ks++) {
            const uint32_t kb = (uint32_t)ks * 32u;
            uint32_t a[2][4];
#pragma unroll
            for (int mf = 0; mf < 2; mf++) {
                uint32_t addr = sA + aRow[mf] + ((kb + aHi) ^ aXor[mf]);
                LDSM_X4(a[mf][0], a[mf][1], a[mf][2], a[mf][3], addr);
            }
            uint32_t b[4][4];
#pragma unroll
            for (int g = 0; g < 4; g++) {
                uint32_t addr = sB + bRow[g] + ((kb + bHi) ^ bXor[g]);
                LDSM_X4(b[g][0], b[g][1], b[g][2], b[g][3], addr);
            }

            /* after the LAST ks's LDSMs, this warp has read everything it
               will ever read from stage s -> release it before the MMAs */
            if (ks == 3 && lane == 0) MBARRIER_ARRIVE(mbar_base + 32 + s * 8);

#pragma unroll
            for (int mf = 0; mf < 2; mf++) {
#pragma unroll
                for (int nf = 0; nf < 8; nf++) {
                    const int g  = nf >> 1;
                    const int hi = (nf & 1) * 2;
                    MMA16816(acc[mf][nf][0], acc[mf][nf][1], acc[mf][nf][2], acc[mf][nf][3],
                             a[mf][0], a[mf][1], a[mf][2], a[mf][3],
                             b[g][hi], b[g][hi + 1]);
                }
            }
        }
    }

    /* epilogue: out = acc + bias */
    const int colBase = nt * BN + warp_n * 64 + (lane & 3) * 2;
    const float* brow = bias + (size_t)e * DN;
#pragma unroll
    for (int mf = 0; mf < 2; mf++) {
#pragma unroll
        for (int half = 0; half < 2; half++) {
            const int r = warp_m * 32 + mf * 16 + (lane >> 2) + half * 8;
            if (r < nrows) {
                float* orow = out + (size_t)(row0 + r) * DN;
#pragma unroll
                for (int nf = 0; nf < 8; nf++) {
                    const int col = colBase + nf * 8;
                    float2 v;
                    v.x = acc[mf][nf][half * 2 + 0] + brow[col];
                    v.y = acc[mf][nf][half * 2 + 1] + brow[col + 1];
                    *(float2*)(orow + col) = v;
                }
            }
        }
    }
}

/* ---------------- host launcher ---------------- */
extern "C" void kernel_launch(void* const* d_in, const int* in_sizes, int n_in,
                              void* d_out, int out_size)
{
    const float* x    = (const float*)d_in[0];
    const int*   ef   = (const int*)d_in[1];
    const float* w    = (const float*)d_in[2];
    const float* bias = (const float*)d_in[3];
    float* out = (float*)d_out;

    const long long T = (long long)in_sizes[0] / DK;

    const long long nA16 = T * DK / 16;
    const long long nW16 = (long long)E_NUM * DN * DK / 16;
    cvt_all_kernel<<<4736, 256>>>((const float4*)w, (const float4*)x, nW16, nA16);
    build_tiles_kernel<<<1, 32>>>(ef, (int)T);

    cudaFuncSetAttribute(gemm_kernel, cudaFuncAttributeMaxDynamicSharedMemorySize, SMEM_TOTAL);

    const int mt_max = (int)((T + BM - 1) / BM) + E_NUM;   /* ~1056 */
    dim3 grid(DN / BN, (unsigned)mt_max);                  /* (8, ~1056) */
    gemm_kernel<<<grid, 256, SMEM_TOTAL>>>(bias, out, (int)T);
}

// round 11
// speedup vs baseline: 1.3819x; 1.0204x over previous
#include <cuda_runtime.h>
#include <cuda_fp16.h>
#include <cstdint>

#define E_NUM 32
#define DK 1024
#define DN 1024
#define BM 128
#define BN 128
#define KC 64            /* fp16 per K-chunk = 128 bytes/row */
#define NCHUNK (DK / KC) /* 16 */
#define STAGES 3
#define MT_CAP 1152
#define TMAX 131072LL

/* ---------------- scratch (device globals; no allocation APIs) -------------- */
static __device__ __align__(1024) __half g_Ah[TMAX * DK];                   /* 256 MB */
static __device__ __align__(1024) __half g_Wh[(long long)E_NUM * DN * DK];  /* 64 MB  */
static __device__ int g_tile_expert[MT_CAP];
static __device__ int g_tile_row[MT_CAP];
static __device__ int g_tile_nrows[MT_CAP];
static __device__ int g_num_mtiles;

/* ---------------- helpers ---------------- */
static __device__ __forceinline__ uint32_t smem_u32(const void* p) {
    uint32_t a;
    asm("{ .reg .u64 t; cvta.to.shared.u64 t, %1; cvt.u32.u64 %0, t; }" : "=r"(a) : "l"(p));
    return a;
}
static __device__ __forceinline__ void cp16(uint32_t dst, const void* src, int src_size) {
    asm volatile("cp.async.cg.shared.global [%0], [%1], 16, %2;\n"
                 :: "r"(dst), "l"(src), "r"(src_size));
}
static __device__ __forceinline__ void cp_async_arrive(uint32_t mbar) {
    asm volatile("cp.async.mbarrier.arrive.noinc.shared.b64 [%0];" :: "r"(mbar) : "memory");
}

#define MBARRIER_INIT(addr, cnt) \
    asm volatile("mbarrier.init.shared.b64 [%0], %1;" :: "r"((uint32_t)(addr)), "r"((uint32_t)(cnt)) : "memory")
#define MBARRIER_ARRIVE(addr) \
    asm volatile("mbarrier.arrive.shared.b64 _, [%0];" :: "r"((uint32_t)(addr)) : "memory")

/* acquire wait: consumer side (generic-proxy LDS reads follow) */
#define MBARRIER_WAIT_PARITY(mbar_smem_addr, phase_parity) do {                                   \
    uint32_t _mbar = (uint32_t)(mbar_smem_addr);                                                  \
    uint32_t _parity = (uint32_t)(phase_parity);                                                  \
    uint32_t _done;                                                                               \
    asm volatile(                                                                                 \
        "{\n\t"                                                                                   \
        ".reg .pred p;\n\t"                                                                       \
        "mbarrier.try_wait.parity.acquire.cta.shared::cta.b64 p, [%1], %2;\n\t"                   \
        "selp.b32 %0, 1, 0, p;\n\t"                                                               \
        "}"                                                                                       \
        : "=r"(_done) : "r"(_mbar), "r"(_parity) : "memory");                                     \
    if (!_done) {                                                                                 \
        asm volatile(                                                                             \
            "{\n\t"                                                                               \
            ".reg .pred P1;\n\t"                                                                  \
            "WAIT_LOOP_%=:\n\t"                                                                   \
            "mbarrier.try_wait.parity.acquire.cta.shared::cta.b64 P1, [%0], %1, 0x989680;\n\t"    \
            "@P1 bra.uni WAIT_DONE_%=;\n\t"                                                       \
            "bra.uni WAIT_LOOP_%=;\n\t"                                                           \
            "WAIT_DONE_%=:\n\t"                                                                   \
            "}"                                                                                   \
            :: "r"(_mbar), "r"(_parity) : "memory");                                              \
    }                                                                                             \
} while (0)

/* relaxed wait: producer side (only async-proxy cp.async writes follow) */
#define MBARRIER_WAIT_PARITY_RELAXED(mbar_smem_addr, phase_parity) do {                           \
    uint32_t _mbar = (uint32_t)(mbar_smem_addr);                                                  \
    uint32_t _parity = (uint32_t)(phase_parity);                                                  \
    uint32_t _done;                                                                               \
    asm volatile(                                                                                 \
        "{\n\t"                                                                                   \
        ".reg .pred p;\n\t"                                                                       \
        "mbarrier.try_wait.parity.relaxed.cta.shared::cta.b64 p, [%1], %2;\n\t"                   \
        "selp.b32 %0, 1, 0, p;\n\t"                                                               \
        "}"                                                                                       \
        : "=r"(_done) : "r"(_mbar), "r"(_parity) : "memory");                                     \
    if (!_done) {                                                                                 \
        asm volatile(                                                                             \
            "{\n\t"                                                                               \
            ".reg .pred P1;\n\t"                                                                  \
            "WAIT_LOOP_%=:\n\t"                                                                   \
            "mbarrier.try_wait.parity.relaxed.cta.shared::cta.b64 P1, [%0], %1, 0x989680;\n\t"    \
            "@P1 bra.uni WAIT_DONE_%=;\n\t"                                                       \
            "bra.uni WAIT_LOOP_%=;\n\t"                                                           \
            "WAIT_DONE_%=:\n\t"                                                                   \
            "}"                                                                                   \
            :: "r"(_mbar), "r"(_parity) : "memory");                                              \
    }                                                                                             \
} while (0)

#define LDSM_X4(r0, r1, r2, r3, addr) \
    asm volatile("ldmatrix.sync.aligned.m8n8.x4.shared.b16 {%0,%1,%2,%3}, [%4];" \
                 : "=r"(r0), "=r"(r1), "=r"(r2), "=r"(r3) : "r"(addr))

#define MMA16816(c0, c1, c2, c3, a0, a1, a2, a3, b0, b1) \
    asm volatile("mma.sync.aligned.m16n8k16.row.col.f32.f16.f16.f32 " \
                 "{%0,%1,%2,%3}, {%4,%5,%6,%7}, {%8,%9}, {%0,%1,%2,%3};" \
                 : "+f"(c0), "+f"(c1), "+f"(c2), "+f"(c3) \
                 : "r"(a0), "r"(a1), "r"(a2), "r"(a3), "r"(b0), "r"(b1))

/* -------- fused fp32->fp16 conversion (32B/thread-iter, evict-first reads)
   + integrated tile-table build: the LAST block builds the tile table while
   the remaining gridDim.x-1 blocks do the bulk conversion.                  -- */
__global__ void cvt_all_kernel(const float4* __restrict__ srcW,
                               const float4* __restrict__ srcA,
                               long long nW16, long long nA16,
                               const int* __restrict__ ef, int T_tokens) {
    if (blockIdx.x == gridDim.x - 1) {
        /* tile-table block: thread 0 builds; handles int32 OR int64 ef */
        if (threadIdx.x == 0) {
            long long s = 0;
            for (int i = 0; i < E_NUM; i++) s += ef[i];
            bool is64 = (s != (long long)T_tokens);
            long long off = 0;
            int t = 0;
            for (int e = 0; e < E_NUM; e++) {
                long long c;
                if (is64)
                    c = (long long)(unsigned)ef[2 * e] | ((long long)ef[2 * e + 1] << 32);
                else
                    c = ef[e];
                for (long long m = 0; m < c; m += BM) {
                    long long rem = c - m;
                    g_tile_expert[t] = e;
                    g_tile_row[t]    = (int)(off + m);
                    g_tile_nrows[t]  = (int)(rem < BM ? rem : BM);
                    t++;
                }
                off += c;
            }
            g_num_mtiles = t;
        }
        return;
    }

    const long long nbulk = (long long)(gridDim.x - 1) * blockDim.x;
    long long i = (long long)blockIdx.x * blockDim.x + threadIdx.x;
    uint4* dstW = reinterpret_cast<uint4*>(g_Wh);
    uint4* dstA = reinterpret_cast<uint4*>(g_Ah);
    const long long ntot = nW16 + nA16;
    for (; i < ntot; i += nbulk) {
        const bool isW = (i < nW16);
        const long long j = isW ? i : (i - nW16);
        const float4* s = isW ? (srcW + 4 * j) : (srcA + 4 * j);
        /* single-use streaming reads: evict-first */
        float4 v0 = __ldcs(s + 0);
        float4 v1 = __ldcs(s + 1);
        float4 v2 = __ldcs(s + 2);
        float4 v3 = __ldcs(s + 3);
        __half2 h;
        uint4 u0, u1;
        h = __floats2half2_rn(v0.x, v0.y); u0.x = *(uint32_t*)&h;
        h = __floats2half2_rn(v0.z, v0.w); u0.y = *(uint32_t*)&h;
        h = __floats2half2_rn(v1.x, v1.y); u0.z = *(uint32_t*)&h;
        h = __floats2half2_rn(v1.z, v1.w); u0.w = *(uint32_t*)&h;
        h = __floats2half2_rn(v2.x, v2.y); u1.x = *(uint32_t*)&h;
        h = __floats2half2_rn(v2.z, v2.w); u1.y = *(uint32_t*)&h;
        h = __floats2half2_rn(v3.x, v3.y); u1.z = *(uint32_t*)&h;
        h = __floats2half2_rn(v3.z, v3.w); u1.w = *(uint32_t*)&h;
        if (isW) { dstW[2 * j] = u0; dstW[2 * j + 1] = u1; }
        else     { dstA[2 * j] = u0; dstA[2 * j + 1] = u1; }
    }
}

/* ---------------- main grouped-GEMM kernel (mma.sync fp16) ----------------
   R10 config: CTA 128x128, 8 warps (4m x 2n), warp 32x64, K-chunk 64,
   3-stage mbarrier full/empty pipeline, early empty release after last
   LDSMs, relaxed producer waits, 2 CTAs/SM.
   NEW vs R10: bias row prefetched into L2 at CTA start so the epilogue's
   bias loads do not stall on DRAM at the tail.                               */

#define STAGE_BYTES 32768              /* A 16KB + B 16KB */
#define MBAR_BYTES  1024
#define SMEM_TOTAL  (STAGES * STAGE_BYTES + MBAR_BYTES)
/* mbar layout: full[s] at +s*8; empty[s] at +32+s*8 */

static __device__ __forceinline__ void produce_chunk(
    int cc, uint32_t smem_base, uint32_t mbar_base,
    const __half* __restrict__ gA, const __half* __restrict__ gB,
    int a_sz, int tid, uint32_t* emptyph)
{
    const int s = cc % STAGES;
    if (cc >= STAGES) {   /* first use of each stage needs no empty-wait */
        MBARRIER_WAIT_PARITY_RELAXED(mbar_base + 32 + s * 8, (*emptyph >> s) & 1);
        *emptyph ^= (1u << s);
    }
    const int row  = tid >> 1;
    const int j0   = (tid & 1) * 4;
    const uint32_t xorv = (uint32_t)(row & 7) * 16u;
    uint32_t sA = smem_base + (uint32_t)s * STAGE_BYTES + (uint32_t)row * 128u;
    uint32_t sB = sA + 16384u;
    const char* srcA = (const char*)(gA + (size_t)row * DK + (size_t)cc * KC) + j0 * 16;
    const char* srcB = (const char*)(gB + (size_t)row * DK + (size_t)cc * KC) + j0 * 16;
#pragma unroll
    for (int j = 0; j < 4; j++) {
        uint32_t col = ((uint32_t)(j0 + j) * 16u) ^ xorv;
        cp16(sA + col, srcA + j * 16, a_sz);
        cp16(sB + col, srcB + j * 16, 16);
    }
    cp_async_arrive(mbar_base + s * 8);
}

__global__ void __launch_bounds__(256, 2) gemm_kernel(
    const float* __restrict__ bias, float* __restrict__ out, int T_tokens)
{
    extern __shared__ __align__(1024) char smem[];
    const int nt = blockIdx.x;           /* fast dim: 8 N-tiles share A tile in L2 */
    const int mt = blockIdx.y;
    if (mt >= g_num_mtiles) return;

    const int e     = g_tile_expert[mt];
    const int row0  = g_tile_row[mt];
    const int nrows = g_tile_nrows[mt];

    const uint32_t smem_base = smem_u32(smem);
    const uint32_t mbar_base = smem_base + STAGES * STAGE_BYTES;
    const int tid  = threadIdx.x;
    const int lane = tid & 31;
    const int wid  = tid >> 5;
    const int warp_m = wid >> 1;         /* 0..3 */
    const int warp_n = wid & 1;          /* 0..1 */

    /* warm L2 with this CTA's bias row (512B) so the epilogue doesn't stall */
    const float* brow_base = bias + (size_t)e * DN + (size_t)nt * BN;
    if (tid < 4)
        asm volatile("prefetch.global.L2 [%0];" :: "l"(brow_base + tid * 32));

    if (tid == 0) {
#pragma unroll
        for (int s = 0; s < STAGES; s++) {
            MBARRIER_INIT(mbar_base + s * 8, 256);       /* full  */
            MBARRIER_INIT(mbar_base + 32 + s * 8, 8);    /* empty */
        }
    }
    __syncthreads();

    /* global load setup */
    const int arow = tid >> 1;
    const int a_sz = (row0 + arow < T_tokens) ? 16 : 0;
    const __half* gA = g_Ah + (size_t)row0 * DK;
    const __half* gB = g_Wh + ((size_t)e * DN + (size_t)nt * BN) * DK;

    /* ldmatrix per-lane address components */
    uint32_t aRow[2], aXor[2];
#pragma unroll
    for (int mf = 0; mf < 2; mf++) {
        int r = warp_m * 32 + mf * 16 + (lane & 15);
        aRow[mf] = (uint32_t)r * 128u;
        aXor[mf] = (uint32_t)(r & 7) * 16u;
    }
    const uint32_t aHi = (uint32_t)((lane >> 4) & 1) * 16u;

    uint32_t bRow[4], bXor[4];
#pragma unroll
    for (int g = 0; g < 4; g++) {
        int r = warp_n * 64 + g * 16 + (lane & 7) + (((lane >> 4) & 1) << 3);
        bRow[g] = (uint32_t)r * 128u;
        bXor[g] = (uint32_t)(r & 7) * 16u;
    }
    const uint32_t bHi = (uint32_t)((lane >> 3) & 1) * 16u;

    float acc[2][8][4];
#pragma unroll
    for (int mf = 0; mf < 2; mf++)
#pragma unroll
        for (int nf = 0; nf < 8; nf++)
#pragma unroll
            for (int k = 0; k < 4; k++) acc[mf][nf][k] = 0.0f;

    uint32_t fullph = 0, emptyph = 0;

    /* prologue: chunks 0 and 1 (no waits: first use of stages 0,1) */
    produce_chunk(0, smem_base, mbar_base, gA, gB, a_sz, tid, &emptyph);
    produce_chunk(1, smem_base, mbar_base, gA, gB, a_sz, tid, &emptyph);

#pragma unroll 1
    for (int c = 0; c < NCHUNK; c++) {
        const int s = c % STAGES;

        /* produce chunk c+2 (its stage was released during chunk c-1) */
        if (c + 2 < NCHUNK)
            produce_chunk(c + 2, smem_base, mbar_base, gA, gB, a_sz, tid, &emptyph);

        /* consume chunk c: per-warp wait on full[s] */
        MBARRIER_WAIT_PARITY(mbar_base + s * 8, (fullph >> s) & 1);
        fullph ^= (1u << s);

        const uint32_t sA = smem_base + (uint32_t)s * STAGE_BYTES;
        const uint32_t sB = sA + 16384u;

#pragma unroll
        for (int ks = 0; ks < 4; ks++) {
            const uint32_t kb = (uint32_t)ks * 32u;
            uint32_t a[2][4];
#pragma unroll
            for (int mf = 0; mf < 2; mf++) {
                uint32_t addr = sA + aRow[mf] + ((kb + aHi) ^ aXor[mf]);
                LDSM_X4(a[mf][0], a[mf][1], a[mf][2], a[mf][3], addr);
            }
            uint32_t b[4][4];
#pragma unroll
            for (int g = 0; g < 4; g++) {
                uint32_t addr = sB + bRow[g] + ((kb + bHi) ^ bXor[g]);
                LDSM_X4(b[g][0], b[g][1], b[g][2], b[g][3], addr);
            }

            /* after the LAST ks's LDSMs, this warp has read everything it
               will ever read from stage s -> release it before the MMAs */
            if (ks == 3 && lane == 0) MBARRIER_ARRIVE(mbar_base + 32 + s * 8);

#pragma unroll
            for (int mf = 0; mf < 2; mf++) {
#pragma unroll
                for (int nf = 0; nf < 8; nf++) {
                    const int g  = nf >> 1;
                    const int hi = (nf & 1) * 2;
                    MMA16816(acc[mf][nf][0], acc[mf][nf][1], acc[mf][nf][2], acc[mf][nf][3],
                             a[mf][0], a[mf][1], a[mf][2], a[mf][3],
                             b[g][hi], b[g][hi + 1]);
                }
            }
        }
    }

    /* epilogue: out = acc + bias */
    const int colBase = nt * BN + warp_n * 64 + (lane & 3) * 2;
    const float* brow = bias + (size_t)e * DN;
#pragma unroll
    for (int mf = 0; mf < 2; mf++) {
#pragma unroll
        for (int half = 0; half < 2; half++) {
            const int r = warp_m * 32 + mf * 16 + (lane >> 2) + half * 8;
            if (r < nrows) {
                float* orow = out + (size_t)(row0 + r) * DN;
#pragma unroll
                for (int nf = 0; nf < 8; nf++) {
                    const int col = colBase + nf * 8;
                    float2 v;
                    v.x = acc[mf][nf][half * 2 + 0] + brow[col];
                    v.y = acc[mf][nf][half * 2 + 1] + brow[col + 1];
                    *(float2*)(orow + col) = v;
                }
            }
        }
    }
}

/* ---------------- host launcher ---------------- */
extern "C" void kernel_launch(void* const* d_in, const int* in_sizes, int n_in,
                              void* d_out, int out_size)
{
    const float* x    = (const float*)d_in[0];
    const int*   ef   = (const int*)d_in[1];
    const float* w    = (const float*)d_in[2];
    const float* bias = (const float*)d_in[3];
    float* out = (float*)d_out;

    const long long T = (long long)in_sizes[0] / DK;

    const long long nA16 = T * DK / 16;
    const long long nW16 = (long long)E_NUM * DN * DK / 16;
    /* 4736 bulk blocks + 1 tile-table block */
    cvt_all_kernel<<<4737, 256>>>((const float4*)w, (const float4*)x, nW16, nA16,
                                  ef, (int)T);

    cudaFuncSetAttribute(gemm_kernel, cudaFuncAttributeMaxDynamicSharedMemorySize, SMEM_TOTAL);

    const int mt_max = (int)((T + BM - 1) / BM) + E_NUM;   /* ~1056 */
    dim3 grid(DN / BN, (unsigned)mt_max);                  /* (8, ~1056) */
    gemm_kernel<<<grid, 256, SMEM_TOTAL>>>(bias, out, (int)T);
}